// round 6
// baseline (speedup 1.0000x reference)
#include <cuda_runtime.h>
#include <cuda_bf16.h>
#include <cstdint>

// ============================================================================
// SparseLinear: out[M=8192, N=4096] = X[M,K=4096] @ (W*mask)^T
// Toolchain constraint: harness compiles PTX at .target sm_103 (no 'a'), so
// tcgen05/TMEM/TMA-a are unavailable. Use baseline-PTX tensor path:
//   mma.sync.aligned.m16n8k16.row.col.f32.bf16.bf16.f32  (sm_80 feature)
//   ldmatrix.m8n8.x4 + cp.async double-buffered SMEM pipeline.
// Precision: fp32 -> bf16 hi/lo split, 3 products (hh + hl + lh), fp32 accum.
// R4 fingerprint analysis: mask arrives as INT32 (rel_err was exactly
// sqrt(1.2) = the uint8-misread-of-int32 signature). Read it as int32.
// ============================================================================

#define DIN   4096
#define DOUT  4096
#define MTOT  8192
#define BM    128
#define BN    128
#define BK    64
#define KCH   (DIN / BK)        // 64 chunks
#define NTILES (DOUT / BN)      // 32
#define MTILES (MTOT / BM)      // 64

// SMEM: 4 tiles (Xh, Xl, Wh, Wl) per buffer, 128 rows x 128B data, rows padded
// to 144B (conflict-free for ldmatrix and cp.async 16B store phases).
#define PADB   144
#define TILEB  (128 * PADB)     // 18432
#define BUFB   (4 * TILEB)      // 73728
#define SMEMB  (2 * BUFB)       // 147456

// ---------------------------------------------------------------------------
// Device-global bf16 hi/lo scratch (allocation-free rule).
// ---------------------------------------------------------------------------
__device__ __nv_bfloat16 g_Xhi[(size_t)MTOT * DIN];
__device__ __nv_bfloat16 g_Xlo[(size_t)MTOT * DIN];
__device__ __nv_bfloat16 g_Whi[(size_t)DOUT * DIN];
__device__ __nv_bfloat16 g_Wlo[(size_t)DOUT * DIN];

// ---------------------------------------------------------------------------
// PTX helpers (all baseline sm_80-class instructions — compile at sm_103)
// ---------------------------------------------------------------------------
__device__ __forceinline__ uint32_t smem_to_u32(const void* p) {
    uint32_t a;
    asm("{ .reg .u64 t; cvta.to.shared.u64 t, %1; cvt.u32.u64 %0, t; }"
        : "=r"(a) : "l"(p));
    return a;
}

#define CP_ASYNC16(sa, ga) \
    asm volatile("cp.async.cg.shared.global [%0], [%1], 16;" \
        :: "r"(sa), "l"(ga))

#define CP_COMMIT() asm volatile("cp.async.commit_group;" ::: "memory")
#define CP_WAIT0()  asm volatile("cp.async.wait_group 0;" ::: "memory")
#define CP_WAIT1()  asm volatile("cp.async.wait_group 1;" ::: "memory")

#define LDSM4(r, addr) \
    asm volatile("ldmatrix.sync.aligned.m8n8.x4.shared.b16 {%0,%1,%2,%3}, [%4];" \
        : "=r"((r)[0]), "=r"((r)[1]), "=r"((r)[2]), "=r"((r)[3]) \
        : "r"(addr))

#define MMA16816(d, a, b0, b1) \
    asm volatile( \
        "mma.sync.aligned.m16n8k16.row.col.f32.bf16.bf16.f32 " \
        "{%0,%1,%2,%3}, {%4,%5,%6,%7}, {%8,%9}, {%0,%1,%2,%3};" \
        : "+f"((d)[0]), "+f"((d)[1]), "+f"((d)[2]), "+f"((d)[3]) \
        : "r"((a)[0]), "r"((a)[1]), "r"((a)[2]), "r"((a)[3]), \
          "r"(b0), "r"(b1))

// ---------------------------------------------------------------------------
// Prep kernels: mask fuse + fp32 -> bf16 hi/lo split
// ---------------------------------------------------------------------------
__device__ __forceinline__ void split4(float a, float b, float c, float d,
                                       uint2& hp, uint2& lp) {
    __nv_bfloat16 h0 = __float2bfloat16(a), h1 = __float2bfloat16(b);
    __nv_bfloat16 h2 = __float2bfloat16(c), h3 = __float2bfloat16(d);
    __nv_bfloat16 l0 = __float2bfloat16(a - __bfloat162float(h0));
    __nv_bfloat16 l1 = __float2bfloat16(b - __bfloat162float(h1));
    __nv_bfloat16 l2 = __float2bfloat16(c - __bfloat162float(h2));
    __nv_bfloat16 l3 = __float2bfloat16(d - __bfloat162float(h3));
    hp.x = (uint32_t)__bfloat16_as_ushort(h0) | ((uint32_t)__bfloat16_as_ushort(h1) << 16);
    hp.y = (uint32_t)__bfloat16_as_ushort(h2) | ((uint32_t)__bfloat16_as_ushort(h3) << 16);
    lp.x = (uint32_t)__bfloat16_as_ushort(l0) | ((uint32_t)__bfloat16_as_ushort(l1) << 16);
    lp.y = (uint32_t)__bfloat16_as_ushort(l2) | ((uint32_t)__bfloat16_as_ushort(l3) << 16);
}

__global__ void prep_x_kernel(const float* __restrict__ x) {
    size_t i = ((size_t)blockIdx.x * blockDim.x + threadIdx.x) * 4;
    float4 v = *reinterpret_cast<const float4*>(x + i);
    uint2 hp, lp;
    split4(v.x, v.y, v.z, v.w, hp, lp);
    *reinterpret_cast<uint2*>(g_Xhi + i) = hp;
    *reinterpret_cast<uint2*>(g_Xlo + i) = lp;
}

__global__ void prep_w_kernel(const float* __restrict__ w,
                              const int* __restrict__ mk) {
    size_t i = ((size_t)blockIdx.x * blockDim.x + threadIdx.x) * 4;
    float4 v = *reinterpret_cast<const float4*>(w + i);
    int4 m = *reinterpret_cast<const int4*>(mk + i);   // int32 mask, 1 per elem
    float a = m.x ? v.x : 0.0f;
    float b = m.y ? v.y : 0.0f;
    float c = m.z ? v.z : 0.0f;
    float d = m.w ? v.w : 0.0f;
    uint2 hp, lp;
    split4(a, b, c, d, hp, lp);
    *reinterpret_cast<uint2*>(g_Whi + i) = hp;
    *reinterpret_cast<uint2*>(g_Wlo + i) = lp;
}

// ---------------------------------------------------------------------------
// GEMM kernel: 128x128 CTA tile, 8 warps (2 M x 4 N), 64x32 warp tile.
// ---------------------------------------------------------------------------
__device__ __forceinline__ void issue_chunk(
    uint32_t smb, int buf, int c, int tid,
    const __nv_bfloat16* const* tp /* [4] tile base pointers */) {
#pragma unroll
    for (int j = 0; j < 16; j++) {
        // idx = tid + j*256 in [0, 4096): tile = j>>2 (compile-time),
        // row = 32*(j&3) + tid/8, seg = tid&7. Each 16B segment.
        const int tile = j >> 2;
        int row = 32 * (j & 3) + (tid >> 3);
        int seg = tid & 7;
        const __nv_bfloat16* gp = tp[tile] + (size_t)row * DIN + c * BK + seg * 8;
        uint32_t sa = smb + buf * BUFB + tile * TILEB + row * PADB + seg * 16;
        CP_ASYNC16(sa, gp);
    }
    CP_COMMIT();
}

__global__ __launch_bounds__(256, 1)
void sparse_linear_hmma_kernel(float* __restrict__ out) {
    extern __shared__ __align__(16) char sm[];
    uint32_t smb = smem_to_u32(sm);
    const int tid  = threadIdx.x;
    const int wid  = tid >> 5;
    const int lane = tid & 31;
    const int wm = (wid >> 2) * 64;   // warp M offset within CTA (0 or 64)
    const int wn = (wid & 3) * 32;    // warp N offset within CTA (0..96)

    const size_t mbase = (size_t)blockIdx.y * BM;
    const size_t nbase = (size_t)blockIdx.x * BN;

    const __nv_bfloat16* tp[4] = {
        g_Xhi + mbase * DIN, g_Xlo + mbase * DIN,
        g_Whi + nbase * DIN, g_Wlo + nbase * DIN
    };

    float acc[4][4][4];
#pragma unroll
    for (int mi = 0; mi < 4; mi++)
#pragma unroll
        for (int ni = 0; ni < 4; ni++)
#pragma unroll
            for (int q = 0; q < 4; q++) acc[mi][ni][q] = 0.0f;

    // ldmatrix lane addressing (144B padded rows -> conflict-free):
    // A (16x16 per m16 tile): lanes 0-15 rows 0-15 @kb, 16-31 same rows @kb+16
    const int arow_l = lane & 15;
    const int akb_l  = (lane >> 4) << 4;
    // B (two n8 groups per x4): lanes 0-7 rows g*16+0..7 @kb, 8-15 same @kb+16,
    //                           16-23 rows g*16+8..15 @kb, 24-31 same @kb+16
    const int brow_l = (lane & 7) + ((lane >> 4) << 3);
    const int bkb_l  = ((lane >> 3) & 1) << 4;

    // Prologue: chunk 0 into buffer 0.
    issue_chunk(smb, 0, 0, tid, tp);

#pragma unroll 1
    for (int c = 0; c < KCH; c++) {
        const int buf = c & 1;
        if (c + 1 < KCH) {
            issue_chunk(smb, buf ^ 1, c + 1, tid, tp);
            CP_WAIT1();
        } else {
            CP_WAIT0();
        }
        __syncthreads();

        const uint32_t tb = smb + buf * BUFB;
#pragma unroll
        for (int ks = 0; ks < 4; ks++) {
            uint32_t Ah[16], Al[16], Bh[8], Bl[8];
            const int akb = ks * 32 + akb_l;
            const int bkb = ks * 32 + bkb_l;
#pragma unroll
            for (int mi = 0; mi < 4; mi++) {
                uint32_t ra = tb + (wm + mi * 16 + arow_l) * PADB + akb;
                LDSM4(&Ah[mi * 4], ra);
                LDSM4(&Al[mi * 4], ra + TILEB);
            }
#pragma unroll
            for (int g = 0; g < 2; g++) {
                uint32_t rb = tb + 2 * TILEB + (wn + g * 16 + brow_l) * PADB + bkb;
                LDSM4(&Bh[g * 4], rb);
                LDSM4(&Bl[g * 4], rb + TILEB);
            }
#pragma unroll
            for (int mi = 0; mi < 4; mi++)
#pragma unroll
                for (int ni = 0; ni < 4; ni++) {
                    MMA16816(acc[mi][ni], &Ah[mi * 4], Bh[ni * 2], Bh[ni * 2 + 1]);
                    MMA16816(acc[mi][ni], &Ah[mi * 4], Bl[ni * 2], Bl[ni * 2 + 1]);
                    MMA16816(acc[mi][ni], &Al[mi * 4], Bh[ni * 2], Bh[ni * 2 + 1]);
                }
        }
        __syncthreads();
    }

    // Epilogue: c-frag layout -> direct float2 stores.
    const int r0 = lane >> 2;
    const int cc = 2 * (lane & 3);
#pragma unroll
    for (int mi = 0; mi < 4; mi++) {
#pragma unroll
        for (int ni = 0; ni < 4; ni++) {
            size_t row = mbase + wm + mi * 16 + r0;
            size_t col = nbase + wn + ni * 8 + cc;
            float2 v0 = make_float2(acc[mi][ni][0], acc[mi][ni][1]);
            float2 v1 = make_float2(acc[mi][ni][2], acc[mi][ni][3]);
            *reinterpret_cast<float2*>(out + row * DOUT + col) = v0;
            *reinterpret_cast<float2*>(out + (row + 8) * DOUT + col) = v1;
        }
    }
}

// ---------------------------------------------------------------------------
// Launch
// ---------------------------------------------------------------------------
extern "C" void kernel_launch(void* const* d_in, const int* in_sizes, int n_in,
                              void* d_out, int out_size) {
    const float* x  = (const float*)d_in[0];
    const float* w  = (const float*)d_in[1];
    const int*   mk = (const int*)d_in[2];     // bool upcast to int32 by harness
    float* out = (float*)d_out;

    prep_x_kernel<<<((size_t)MTOT * DIN) / 4 / 256, 256>>>(x);
    prep_w_kernel<<<((size_t)DOUT * DIN) / 4 / 256, 256>>>(w, mk);

    cudaFuncSetAttribute(sparse_linear_hmma_kernel,
                         cudaFuncAttributeMaxDynamicSharedMemorySize, SMEMB);
    sparse_linear_hmma_kernel<<<dim3(NTILES, MTILES), 256, SMEMB>>>(out);
}

// round 7
// speedup vs baseline: 1.3992x; 1.3992x over previous
#include <cuda_runtime.h>
#include <cuda_fp16.h>
#include <cstdint>

// ============================================================================
// SparseLinear: out[M=8192, N=4096] = X[M,K=4096] @ (W*mask)^T
// sm_103 (no 'a') toolchain => baseline-PTX tensor path:
//   mma.sync.aligned.m16n8k16.row.col.f32.f16.f16.f32
//   ldmatrix.m8n8.x4 + cp.async 3-stage SMEM pipeline.
// R6 precision model (validated by R5 measurement 9.3e-6 vs 1.5e-5 predicted):
//   fp16 2-product split:  out = (Xh + Xl) @ Wh^T,  Wh = fp16(W*mask).
//   Dominant error = W fp16 rounding, rms ~ 2^-11/sqrt(3) ~ 2.8e-4 < 1e-3.
// vs R5: 33% fewer MMAs, 25% less tile traffic, B-frags shared by both
// products, 3-stage pipeline hides DRAM latency across two chunk-times.
// ============================================================================

#define DIN   4096
#define DOUT  4096
#define MTOT  8192
#define BM    128
#define BN    128
#define BK    64
#define KCH   (DIN / BK)        // 64 chunks
#define NTILES (DOUT / BN)      // 32
#define MTILES (MTOT / BM)      // 64

// SMEM: 3 tiles (Xh, Xl, Wh) per stage, 128 rows x 128B data, rows padded to
// 144B (conflict-free for ldmatrix and cp.async 16B store phases). 3 stages.
#define PADB   144
#define TILEB  (128 * PADB)     // 18432
#define BUFB   (3 * TILEB)      // 55296
#define STAGES 3
#define SMEMB  (STAGES * BUFB)  // 165888

// ---------------------------------------------------------------------------
// Device-global fp16 scratch (allocation-free rule).
// ---------------------------------------------------------------------------
__device__ __half g_Xh[(size_t)MTOT * DIN];
__device__ __half g_Xl[(size_t)MTOT * DIN];
__device__ __half g_Wh[(size_t)DOUT * DIN];

// ---------------------------------------------------------------------------
// PTX helpers (all baseline sm_80-class instructions — compile at sm_103)
// ---------------------------------------------------------------------------
__device__ __forceinline__ uint32_t smem_to_u32(const void* p) {
    uint32_t a;
    asm("{ .reg .u64 t; cvta.to.shared.u64 t, %1; cvt.u32.u64 %0, t; }"
        : "=r"(a) : "l"(p));
    return a;
}

#define CP_ASYNC16(sa, ga) \
    asm volatile("cp.async.cg.shared.global [%0], [%1], 16;" \
        :: "r"(sa), "l"(ga))

#define CP_COMMIT() asm volatile("cp.async.commit_group;" ::: "memory")
#define CP_WAIT0()  asm volatile("cp.async.wait_group 0;" ::: "memory")
#define CP_WAIT1()  asm volatile("cp.async.wait_group 1;" ::: "memory")
#define CP_WAIT2()  asm volatile("cp.async.wait_group 2;" ::: "memory")

#define LDSM4(r, addr) \
    asm volatile("ldmatrix.sync.aligned.m8n8.x4.shared.b16 {%0,%1,%2,%3}, [%4];" \
        : "=r"((r)[0]), "=r"((r)[1]), "=r"((r)[2]), "=r"((r)[3]) \
        : "r"(addr))

#define MMA16816(d, a, b0, b1) \
    asm volatile( \
        "mma.sync.aligned.m16n8k16.row.col.f32.f16.f16.f32 " \
        "{%0,%1,%2,%3}, {%4,%5,%6,%7}, {%8,%9}, {%0,%1,%2,%3};" \
        : "+f"((d)[0]), "+f"((d)[1]), "+f"((d)[2]), "+f"((d)[3]) \
        : "r"((a)[0]), "r"((a)[1]), "r"((a)[2]), "r"((a)[3]), \
          "r"(b0), "r"(b1))

// ---------------------------------------------------------------------------
// Prep kernels: mask fuse + fp32 -> fp16 (hi/lo for X, single for W)
// ---------------------------------------------------------------------------
__global__ void prep_x_kernel(const float* __restrict__ x) {
    size_t i = ((size_t)blockIdx.x * blockDim.x + threadIdx.x) * 4;
    float4 v = *reinterpret_cast<const float4*>(x + i);
    __half h0 = __float2half_rn(v.x), h1 = __float2half_rn(v.y);
    __half h2 = __float2half_rn(v.z), h3 = __float2half_rn(v.w);
    __half l0 = __float2half_rn(v.x - __half2float(h0));
    __half l1 = __float2half_rn(v.y - __half2float(h1));
    __half l2 = __float2half_rn(v.z - __half2float(h2));
    __half l3 = __float2half_rn(v.w - __half2float(h3));
    uint2 hp, lp;
    hp.x = (uint32_t)__half_as_ushort(h0) | ((uint32_t)__half_as_ushort(h1) << 16);
    hp.y = (uint32_t)__half_as_ushort(h2) | ((uint32_t)__half_as_ushort(h3) << 16);
    lp.x = (uint32_t)__half_as_ushort(l0) | ((uint32_t)__half_as_ushort(l1) << 16);
    lp.y = (uint32_t)__half_as_ushort(l2) | ((uint32_t)__half_as_ushort(l3) << 16);
    *reinterpret_cast<uint2*>(g_Xh + i) = hp;
    *reinterpret_cast<uint2*>(g_Xl + i) = lp;
}

__global__ void prep_w_kernel(const float* __restrict__ w,
                              const int* __restrict__ mk) {
    size_t i = ((size_t)blockIdx.x * blockDim.x + threadIdx.x) * 4;
    float4 v = *reinterpret_cast<const float4*>(w + i);
    int4 m = *reinterpret_cast<const int4*>(mk + i);   // int32 mask, 1 per elem
    __half h0 = __float2half_rn(m.x ? v.x : 0.0f);
    __half h1 = __float2half_rn(m.y ? v.y : 0.0f);
    __half h2 = __float2half_rn(m.z ? v.z : 0.0f);
    __half h3 = __float2half_rn(m.w ? v.w : 0.0f);
    uint2 hp;
    hp.x = (uint32_t)__half_as_ushort(h0) | ((uint32_t)__half_as_ushort(h1) << 16);
    hp.y = (uint32_t)__half_as_ushort(h2) | ((uint32_t)__half_as_ushort(h3) << 16);
    *reinterpret_cast<uint2*>(g_Wh + i) = hp;
}

// ---------------------------------------------------------------------------
// GEMM kernel: 128x128 CTA tile, 8 warps (2 M x 4 N), 64x32 warp tile.
// ---------------------------------------------------------------------------
__device__ __forceinline__ void issue_chunk(
    uint32_t smb, int buf, int c, int tid,
    const __half* const* tp /* [3] tile base pointers: Xh, Xl, Wh */) {
#pragma unroll
    for (int j = 0; j < 12; j++) {
        // 3 tiles x 128 rows x 8 segs(16B) = 3072 segs / 256 thr = 12 per thr.
        const int tile = j >> 2;                   // compile-time 0..2
        int row = 32 * (j & 3) + (tid >> 3);
        int seg = tid & 7;
        const __half* gp = tp[tile] + (size_t)row * DIN + c * BK + seg * 8;
        uint32_t sa = smb + buf * BUFB + tile * TILEB + row * PADB + seg * 16;
        CP_ASYNC16(sa, gp);
    }
    CP_COMMIT();
}

__global__ __launch_bounds__(256, 1)
void sparse_linear_hmma_kernel(float* __restrict__ out) {
    extern __shared__ __align__(16) char sm[];
    uint32_t smb = smem_to_u32(sm);
    const int tid  = threadIdx.x;
    const int wid  = tid >> 5;
    const int lane = tid & 31;
    const int wm = (wid >> 2) * 64;   // warp M offset within CTA (0 or 64)
    const int wn = (wid & 3) * 32;    // warp N offset within CTA (0..96)

    const size_t mbase = (size_t)blockIdx.y * BM;
    const size_t nbase = (size_t)blockIdx.x * BN;

    const __half* tp[3] = {
        g_Xh + mbase * DIN, g_Xl + mbase * DIN, g_Wh + nbase * DIN
    };

    float acc[4][4][4];
#pragma unroll
    for (int mi = 0; mi < 4; mi++)
#pragma unroll
        for (int ni = 0; ni < 4; ni++)
#pragma unroll
            for (int q = 0; q < 4; q++) acc[mi][ni][q] = 0.0f;

    // ldmatrix lane addressing (144B padded rows -> conflict-free):
    const int arow_l = lane & 15;
    const int akb_l  = (lane >> 4) << 4;
    const int brow_l = (lane & 7) + ((lane >> 4) << 3);
    const int bkb_l  = ((lane >> 3) & 1) << 4;

    // Prologue: stages 0..2.
    issue_chunk(smb, 0, 0, tid, tp);
    issue_chunk(smb, 1, 1, tid, tp);
    issue_chunk(smb, 2, 2, tid, tp);

    int buf = 0;
#pragma unroll 1
    for (int c = 0; c < KCH; c++) {
        // At loop top, chunks issued = min(c+3, KCH). Need chunk c complete:
        if (c <= KCH - 3)      CP_WAIT2();
        else if (c == KCH - 2) CP_WAIT1();
        else                   CP_WAIT0();
        __syncthreads();

        const uint32_t tb = smb + buf * BUFB;
#pragma unroll
        for (int ks = 0; ks < 4; ks++) {
            uint32_t Ah[16], Al[16], Bh[8];
            const int akb = ks * 32 + akb_l;
            const int bkb = ks * 32 + bkb_l;
#pragma unroll
            for (int mi = 0; mi < 4; mi++) {
                uint32_t ra = tb + (wm + mi * 16 + arow_l) * PADB + akb;
                LDSM4(&Ah[mi * 4], ra);
                LDSM4(&Al[mi * 4], ra + TILEB);
            }
#pragma unroll
            for (int g = 0; g < 2; g++) {
                uint32_t rb = tb + 2 * TILEB + (wn + g * 16 + brow_l) * PADB + bkb;
                LDSM4(&Bh[g * 4], rb);
            }
#pragma unroll
            for (int mi = 0; mi < 4; mi++)
#pragma unroll
                for (int ni = 0; ni < 4; ni++) {
                    MMA16816(acc[mi][ni], &Ah[mi * 4], Bh[ni * 2], Bh[ni * 2 + 1]);
                    MMA16816(acc[mi][ni], &Al[mi * 4], Bh[ni * 2], Bh[ni * 2 + 1]);
                }
        }
        __syncthreads();

        if (c + 3 < KCH) issue_chunk(smb, buf, c + 3, tid, tp);
        buf = (buf == STAGES - 1) ? 0 : buf + 1;
    }

    // Epilogue: c-frag layout -> direct float2 stores.
    const int r0 = lane >> 2;
    const int cc = 2 * (lane & 3);
#pragma unroll
    for (int mi = 0; mi < 4; mi++) {
#pragma unroll
        for (int ni = 0; ni < 4; ni++) {
            size_t row = mbase + wm + mi * 16 + r0;
            size_t col = nbase + wn + ni * 8 + cc;
            float2 v0 = make_float2(acc[mi][ni][0], acc[mi][ni][1]);
            float2 v1 = make_float2(acc[mi][ni][2], acc[mi][ni][3]);
            *reinterpret_cast<float2*>(out + row * DOUT + col) = v0;
            *reinterpret_cast<float2*>(out + (row + 8) * DOUT + col) = v1;
        }
    }
}

// ---------------------------------------------------------------------------
// Launch
// ---------------------------------------------------------------------------
extern "C" void kernel_launch(void* const* d_in, const int* in_sizes, int n_in,
                              void* d_out, int out_size) {
    const float* x  = (const float*)d_in[0];
    const float* w  = (const float*)d_in[1];
    const int*   mk = (const int*)d_in[2];     // bool upcast to int32 by harness
    float* out = (float*)d_out;

    prep_x_kernel<<<((size_t)MTOT * DIN) / 4 / 256, 256>>>(x);
    prep_w_kernel<<<((size_t)DOUT * DIN) / 4 / 256, 256>>>(w, mk);

    cudaFuncSetAttribute(sparse_linear_hmma_kernel,
                         cudaFuncAttributeMaxDynamicSharedMemorySize, SMEMB);
    sparse_linear_hmma_kernel<<<dim3(NTILES, MTILES), 256, SMEMB>>>(out);
}

// round 12
// speedup vs baseline: 1.4928x; 1.0669x over previous
#include <cuda_runtime.h>
#include <cuda_fp16.h>
#include <cstdint>

// ============================================================================
// SparseLinear: out[M=8192, N=4096] = X[M,K=4096] @ (W*mask)^T
// sm_103 (no 'a') toolchain => baseline-PTX tensor path:
//   mma.sync.aligned.m16n8k16.row.col.f32.f16.f16.f32
//   ldmatrix.m8n8.x4 + cp.async 4-stage SMEM pipeline.
// Precision lineage (each predicted then measured):
//   R5 bf16 3-prod: pred 1.5e-5, meas 9.3e-6
//   R7 fp16 2-prod: pred 2.8e-4, meas 1.85e-4  (W rounding only)
//   R8 fp16 1-prod: pred sqrt(2)*1.85e-4 ~ 2.6e-4  (X+W rounding, quadrature)
// Time ~ MMA count (R7 scaling matched): halve MMAs again -> ~810-920 us.
// ============================================================================

#define DIN   4096
#define DOUT  4096
#define MTOT  8192
#define BM    128
#define BN    128
#define BK    64
#define KCH   (DIN / BK)        // 64 chunks
#define NTILES (DOUT / BN)      // 32
#define MTILES (MTOT / BM)      // 64

// SMEM: 2 tiles (Xh, Wh) per stage, 128 rows x 128B data, rows padded to
// 144B (conflict-free for ldmatrix and cp.async 16B store phases). 4 stages.
#define PADB   144
#define TILEB  (128 * PADB)     // 18432
#define BUFB   (2 * TILEB)      // 36864
#define STAGES 4
#define SMEMB  (STAGES * BUFB)  // 147456

// ---------------------------------------------------------------------------
// Device-global fp16 scratch (allocation-free rule).
// ---------------------------------------------------------------------------
__device__ __half g_Xh[(size_t)MTOT * DIN];
__device__ __half g_Wh[(size_t)DOUT * DIN];

// ---------------------------------------------------------------------------
// PTX helpers (all baseline sm_80-class instructions — compile at sm_103)
// ---------------------------------------------------------------------------
__device__ __forceinline__ uint32_t smem_to_u32(const void* p) {
    uint32_t a;
    asm("{ .reg .u64 t; cvta.to.shared.u64 t, %1; cvt.u32.u64 %0, t; }"
        : "=r"(a) : "l"(p));
    return a;
}

#define CP_ASYNC16(sa, ga) \
    asm volatile("cp.async.cg.shared.global [%0], [%1], 16;" \
        :: "r"(sa), "l"(ga))

#define CP_COMMIT() asm volatile("cp.async.commit_group;" ::: "memory")
#define CP_WAIT0()  asm volatile("cp.async.wait_group 0;" ::: "memory")
#define CP_WAIT1()  asm volatile("cp.async.wait_group 1;" ::: "memory")
#define CP_WAIT2()  asm volatile("cp.async.wait_group 2;" ::: "memory")
#define CP_WAIT3()  asm volatile("cp.async.wait_group 3;" ::: "memory")

#define LDSM4(r, addr) \
    asm volatile("ldmatrix.sync.aligned.m8n8.x4.shared.b16 {%0,%1,%2,%3}, [%4];" \
        : "=r"((r)[0]), "=r"((r)[1]), "=r"((r)[2]), "=r"((r)[3]) \
        : "r"(addr))

#define MMA16816(d, a, b0, b1) \
    asm volatile( \
        "mma.sync.aligned.m16n8k16.row.col.f32.f16.f16.f32 " \
        "{%0,%1,%2,%3}, {%4,%5,%6,%7}, {%8,%9}, {%0,%1,%2,%3};" \
        : "+f"((d)[0]), "+f"((d)[1]), "+f"((d)[2]), "+f"((d)[3]) \
        : "r"((a)[0]), "r"((a)[1]), "r"((a)[2]), "r"((a)[3]), \
          "r"(b0), "r"(b1))

// ---------------------------------------------------------------------------
// Prep kernels: mask fuse + fp32 -> fp16 round
// ---------------------------------------------------------------------------
__global__ void prep_x_kernel(const float* __restrict__ x) {
    size_t i = ((size_t)blockIdx.x * blockDim.x + threadIdx.x) * 4;
    float4 v = *reinterpret_cast<const float4*>(x + i);
    __half h0 = __float2half_rn(v.x), h1 = __float2half_rn(v.y);
    __half h2 = __float2half_rn(v.z), h3 = __float2half_rn(v.w);
    uint2 hp;
    hp.x = (uint32_t)__half_as_ushort(h0) | ((uint32_t)__half_as_ushort(h1) << 16);
    hp.y = (uint32_t)__half_as_ushort(h2) | ((uint32_t)__half_as_ushort(h3) << 16);
    *reinterpret_cast<uint2*>(g_Xh + i) = hp;
}

__global__ void prep_w_kernel(const float* __restrict__ w,
                              const int* __restrict__ mk) {
    size_t i = ((size_t)blockIdx.x * blockDim.x + threadIdx.x) * 4;
    float4 v = *reinterpret_cast<const float4*>(w + i);
    int4 m = *reinterpret_cast<const int4*>(mk + i);   // int32 mask, 1 per elem
    __half h0 = __float2half_rn(m.x ? v.x : 0.0f);
    __half h1 = __float2half_rn(m.y ? v.y : 0.0f);
    __half h2 = __float2half_rn(m.z ? v.z : 0.0f);
    __half h3 = __float2half_rn(m.w ? v.w : 0.0f);
    uint2 hp;
    hp.x = (uint32_t)__half_as_ushort(h0) | ((uint32_t)__half_as_ushort(h1) << 16);
    hp.y = (uint32_t)__half_as_ushort(h2) | ((uint32_t)__half_as_ushort(h3) << 16);
    *reinterpret_cast<uint2*>(g_Wh + i) = hp;
}

// ---------------------------------------------------------------------------
// GEMM kernel: 128x128 CTA tile, 8 warps (2 M x 4 N), 64x32 warp tile.
// ---------------------------------------------------------------------------
__device__ __forceinline__ void issue_chunk(
    uint32_t smb, int buf, int c, int tid,
    const __half* xh, const __half* wh) {
    // 2 tiles x 128 rows x 8 segs(16B) = 2048 segs / 256 thr = 8 per thread.
#pragma unroll
    for (int j = 0; j < 8; j++) {
        const int tile = j >> 2;                   // compile-time 0..1
        int row = 32 * (j & 3) + (tid >> 3);
        int seg = tid & 7;
        const __half* gp = (tile ? wh : xh) + (size_t)row * DIN + c * BK + seg * 8;
        uint32_t sa = smb + buf * BUFB + tile * TILEB + row * PADB + seg * 16;
        CP_ASYNC16(sa, gp);
    }
    CP_COMMIT();
}

__global__ __launch_bounds__(256, 1)
void sparse_linear_hmma_kernel(float* __restrict__ out) {
    extern __shared__ __align__(16) char sm[];
    uint32_t smb = smem_to_u32(sm);
    const int tid  = threadIdx.x;
    const int wid  = tid >> 5;
    const int lane = tid & 31;
    const int wm = (wid >> 2) * 64;   // warp M offset within CTA (0 or 64)
    const int wn = (wid & 3) * 32;    // warp N offset within CTA (0..96)

    const size_t mbase = (size_t)blockIdx.y * BM;
    const size_t nbase = (size_t)blockIdx.x * BN;

    const __half* xh = g_Xh + mbase * DIN;
    const __half* wh = g_Wh + nbase * DIN;

    float acc[4][4][4];
#pragma unroll
    for (int mi = 0; mi < 4; mi++)
#pragma unroll
        for (int ni = 0; ni < 4; ni++)
#pragma unroll
            for (int q = 0; q < 4; q++) acc[mi][ni][q] = 0.0f;

    // ldmatrix lane addressing (144B padded rows -> conflict-free):
    const int arow_l = lane & 15;
    const int akb_l  = (lane >> 4) << 4;
    const int brow_l = (lane & 7) + ((lane >> 4) << 3);
    const int bkb_l  = ((lane >> 3) & 1) << 4;

    // Prologue: stages 0..3.
    issue_chunk(smb, 0, 0, tid, xh, wh);
    issue_chunk(smb, 1, 1, tid, xh, wh);
    issue_chunk(smb, 2, 2, tid, xh, wh);
    issue_chunk(smb, 3, 3, tid, xh, wh);

    int buf = 0;
#pragma unroll 1
    for (int c = 0; c < KCH; c++) {
        // Chunks issued = min(c+4, KCH). Need chunk c complete:
        if (c <= KCH - 4)      CP_WAIT3();
        else if (c == KCH - 3) CP_WAIT2();
        else if (c == KCH - 2) CP_WAIT1();
        else                   CP_WAIT0();
        __syncthreads();

        const uint32_t tb = smb + buf * BUFB;
#pragma unroll
        for (int ks = 0; ks < 4; ks++) {
            uint32_t Ah[16], Bh[8];
            const int akb = ks * 32 + akb_l;
            const int bkb = ks * 32 + bkb_l;
#pragma unroll
            for (int mi = 0; mi < 4; mi++) {
                uint32_t ra = tb + (wm + mi * 16 + arow_l) * PADB + akb;
                LDSM4(&Ah[mi * 4], ra);
            }
#pragma unroll
            for (int g = 0; g < 2; g++) {
                uint32_t rb = tb + TILEB + (wn + g * 16 + brow_l) * PADB + bkb;
                LDSM4(&Bh[g * 4], rb);
            }
#pragma unroll
            for (int mi = 0; mi < 4; mi++)
#pragma unroll
                for (int ni = 0; ni < 4; ni++)
                    MMA16816(acc[mi][ni], &Ah[mi * 4], Bh[ni * 2], Bh[ni * 2 + 1]);
        }
        __syncthreads();

        if (c + 4 < KCH) issue_chunk(smb, buf, c + 4, tid, xh, wh);
        buf = (buf == STAGES - 1) ? 0 : buf + 1;
    }

    // Epilogue: c-frag layout -> direct float2 stores.
    const int r0 = lane >> 2;
    const int cc = 2 * (lane & 3);
#pragma unroll
    for (int mi = 0; mi < 4; mi++) {
#pragma unroll
        for (int ni = 0; ni < 4; ni++) {
            size_t row = mbase + wm + mi * 16 + r0;
            size_t col = nbase + wn + ni * 8 + cc;
            float2 v0 = make_float2(acc[mi][ni][0], acc[mi][ni][1]);
            float2 v1 = make_float2(acc[mi][ni][2], acc[mi][ni][3]);
            *reinterpret_cast<float2*>(out + row * DOUT + col) = v0;
            *reinterpret_cast<float2*>(out + (row + 8) * DOUT + col) = v1;
        }
    }
}

// ---------------------------------------------------------------------------
// Launch
// ---------------------------------------------------------------------------
extern "C" void kernel_launch(void* const* d_in, const int* in_sizes, int n_in,
                              void* d_out, int out_size) {
    const float* x  = (const float*)d_in[0];
    const float* w  = (const float*)d_in[1];
    const int*   mk = (const int*)d_in[2];     // bool upcast to int32 by harness
    float* out = (float*)d_out;

    prep_x_kernel<<<((size_t)MTOT * DIN) / 4 / 256, 256>>>(x);
    prep_w_kernel<<<((size_t)DOUT * DIN) / 4 / 256, 256>>>(w, mk);

    cudaFuncSetAttribute(sparse_linear_hmma_kernel,
                         cudaFuncAttributeMaxDynamicSharedMemorySize, SMEMB);
    sparse_linear_hmma_kernel<<<dim3(NTILES, MTILES), 256, SMEMB>>>(out);
}

// round 13
// speedup vs baseline: 2.6136x; 1.7508x over previous
#include <cuda_runtime.h>
#include <cuda_fp16.h>
#include <cstdint>

// ============================================================================
// SparseLinear: out[M=8192, N=4096] = X[M,K=4096] @ (W*mask)^T
// sm_103 (no 'a') toolchain => baseline-PTX tensor path:
//   mma.sync.aligned.m16n8k16.row.col.f32.f16.f16.f32
//   ldmatrix.m8n8.x4 + cp.async 3-stage SMEM pipeline, 2 CTAs/SM.
// Precision lineage (predicted -> measured):
//   R5 bf16 3-prod: 1.5e-5 -> 9.3e-6
//   R7 fp16 2-prod: 2.8e-4 -> 1.85e-4
//   R8 fp16 1-prod: 2.6e-4 -> 2.78e-4   (numerics settled)
// R8 post-mortem: halving MMAs gave only -6% => NOT MMA-bound. Fixed cost =
// LDSM latency + barriers with only 2 warps/SMSP (occ=1). This round: 3
// stages (108KB smem) + __launch_bounds__(256,2) => 2 CTAs/SM, 4 warps/SMSP.
// ============================================================================

#define DIN   4096
#define DOUT  4096
#define MTOT  8192
#define BM    128
#define BN    128
#define BK    64
#define KCH   (DIN / BK)        // 64 chunks
#define NTILES (DOUT / BN)      // 32
#define MTILES (MTOT / BM)      // 64

// SMEM: 2 tiles (Xh, Wh) per stage, 128 rows x 128B data, rows padded to
// 144B (conflict-free for ldmatrix and cp.async 16B store phases). 3 stages.
#define PADB   144
#define TILEB  (128 * PADB)     // 18432
#define BUFB   (2 * TILEB)      // 36864
#define STAGES 3
#define SMEMB  (STAGES * BUFB)  // 110592  (x2 CTAs = 221184 < 228KB SM limit)

// ---------------------------------------------------------------------------
// Device-global fp16 scratch (allocation-free rule).
// ---------------------------------------------------------------------------
__device__ __half g_Xh[(size_t)MTOT * DIN];
__device__ __half g_Wh[(size_t)DOUT * DIN];

// ---------------------------------------------------------------------------
// PTX helpers (all baseline sm_80-class instructions — compile at sm_103)
// ---------------------------------------------------------------------------
__device__ __forceinline__ uint32_t smem_to_u32(const void* p) {
    uint32_t a;
    asm("{ .reg .u64 t; cvta.to.shared.u64 t, %1; cvt.u32.u64 %0, t; }"
        : "=r"(a) : "l"(p));
    return a;
}

#define CP_ASYNC16(sa, ga) \
    asm volatile("cp.async.cg.shared.global [%0], [%1], 16;" \
        :: "r"(sa), "l"(ga))

#define CP_COMMIT() asm volatile("cp.async.commit_group;" ::: "memory")
#define CP_WAIT0()  asm volatile("cp.async.wait_group 0;" ::: "memory")
#define CP_WAIT1()  asm volatile("cp.async.wait_group 1;" ::: "memory")
#define CP_WAIT2()  asm volatile("cp.async.wait_group 2;" ::: "memory")

#define LDSM4(r, addr) \
    asm volatile("ldmatrix.sync.aligned.m8n8.x4.shared.b16 {%0,%1,%2,%3}, [%4];" \
        : "=r"((r)[0]), "=r"((r)[1]), "=r"((r)[2]), "=r"((r)[3]) \
        : "r"(addr))

#define MMA16816(d, a, b0, b1) \
    asm volatile( \
        "mma.sync.aligned.m16n8k16.row.col.f32.f16.f16.f32 " \
        "{%0,%1,%2,%3}, {%4,%5,%6,%7}, {%8,%9}, {%0,%1,%2,%3};" \
        : "+f"((d)[0]), "+f"((d)[1]), "+f"((d)[2]), "+f"((d)[3]) \
        : "r"((a)[0]), "r"((a)[1]), "r"((a)[2]), "r"((a)[3]), \
          "r"(b0), "r"(b1))

// ---------------------------------------------------------------------------
// Prep kernels: mask fuse + fp32 -> fp16 round
// ---------------------------------------------------------------------------
__global__ void prep_x_kernel(const float* __restrict__ x) {
    size_t i = ((size_t)blockIdx.x * blockDim.x + threadIdx.x) * 4;
    float4 v = *reinterpret_cast<const float4*>(x + i);
    __half h0 = __float2half_rn(v.x), h1 = __float2half_rn(v.y);
    __half h2 = __float2half_rn(v.z), h3 = __float2half_rn(v.w);
    uint2 hp;
    hp.x = (uint32_t)__half_as_ushort(h0) | ((uint32_t)__half_as_ushort(h1) << 16);
    hp.y = (uint32_t)__half_as_ushort(h2) | ((uint32_t)__half_as_ushort(h3) << 16);
    *reinterpret_cast<uint2*>(g_Xh + i) = hp;
}

__global__ void prep_w_kernel(const float* __restrict__ w,
                              const int* __restrict__ mk) {
    size_t i = ((size_t)blockIdx.x * blockDim.x + threadIdx.x) * 4;
    float4 v = *reinterpret_cast<const float4*>(w + i);
    int4 m = *reinterpret_cast<const int4*>(mk + i);   // int32 mask, 1 per elem
    __half h0 = __float2half_rn(m.x ? v.x : 0.0f);
    __half h1 = __float2half_rn(m.y ? v.y : 0.0f);
    __half h2 = __float2half_rn(m.z ? v.z : 0.0f);
    __half h3 = __float2half_rn(m.w ? v.w : 0.0f);
    uint2 hp;
    hp.x = (uint32_t)__half_as_ushort(h0) | ((uint32_t)__half_as_ushort(h1) << 16);
    hp.y = (uint32_t)__half_as_ushort(h2) | ((uint32_t)__half_as_ushort(h3) << 16);
    *reinterpret_cast<uint2*>(g_Wh + i) = hp;
}

// ---------------------------------------------------------------------------
// GEMM kernel: 128x128 CTA tile, 8 warps (2 M x 4 N), 64x32 warp tile,
// 2 CTAs per SM for cross-CTA latency hiding.
// ---------------------------------------------------------------------------
__device__ __forceinline__ void issue_chunk(
    uint32_t smb, int buf, int c, int tid,
    const __half* xh, const __half* wh) {
    // 2 tiles x 128 rows x 8 segs(16B) = 2048 segs / 256 thr = 8 per thread.
#pragma unroll
    for (int j = 0; j < 8; j++) {
        const int tile = j >> 2;                   // compile-time 0..1
        int row = 32 * (j & 3) + (tid >> 3);
        int seg = tid & 7;
        const __half* gp = (tile ? wh : xh) + (size_t)row * DIN + c * BK + seg * 8;
        uint32_t sa = smb + buf * BUFB + tile * TILEB + row * PADB + seg * 16;
        CP_ASYNC16(sa, gp);
    }
    CP_COMMIT();
}

__global__ __launch_bounds__(256, 2)
void sparse_linear_hmma_kernel(float* __restrict__ out) {
    extern __shared__ __align__(16) char sm[];
    uint32_t smb = smem_to_u32(sm);
    const int tid  = threadIdx.x;
    const int wid  = tid >> 5;
    const int lane = tid & 31;
    const int wm = (wid >> 2) * 64;   // warp M offset within CTA (0 or 64)
    const int wn = (wid & 3) * 32;    // warp N offset within CTA (0..96)

    const size_t mbase = (size_t)blockIdx.y * BM;
    const size_t nbase = (size_t)blockIdx.x * BN;

    const __half* xh = g_Xh + mbase * DIN;
    const __half* wh = g_Wh + nbase * DIN;

    float acc[4][4][4];
#pragma unroll
    for (int mi = 0; mi < 4; mi++)
#pragma unroll
        for (int ni = 0; ni < 4; ni++)
#pragma unroll
            for (int q = 0; q < 4; q++) acc[mi][ni][q] = 0.0f;

    // ldmatrix lane addressing (144B padded rows -> conflict-free):
    const int arow_l = lane & 15;
    const int akb_l  = (lane >> 4) << 4;
    const int brow_l = (lane & 7) + ((lane >> 4) << 3);
    const int bkb_l  = ((lane >> 3) & 1) << 4;

    // Prologue: stages 0..2.
    issue_chunk(smb, 0, 0, tid, xh, wh);
    issue_chunk(smb, 1, 1, tid, xh, wh);
    issue_chunk(smb, 2, 2, tid, xh, wh);

    int buf = 0;
#pragma unroll 1
    for (int c = 0; c < KCH; c++) {
        // Chunks issued = min(c+3, KCH). Need chunk c complete:
        if (c <= KCH - 3)      CP_WAIT2();
        else if (c == KCH - 2) CP_WAIT1();
        else                   CP_WAIT0();
        __syncthreads();

        const uint32_t tb = smb + buf * BUFB;
#pragma unroll
        for (int ks = 0; ks < 4; ks++) {
            uint32_t Ah[16], Bh[8];
            const int akb = ks * 32 + akb_l;
            const int bkb = ks * 32 + bkb_l;
#pragma unroll
            for (int mi = 0; mi < 4; mi++) {
                uint32_t ra = tb + (wm + mi * 16 + arow_l) * PADB + akb;
                LDSM4(&Ah[mi * 4], ra);
            }
#pragma unroll
            for (int g = 0; g < 2; g++) {
                uint32_t rb = tb + TILEB + (wn + g * 16 + brow_l) * PADB + bkb;
                LDSM4(&Bh[g * 4], rb);
            }
#pragma unroll
            for (int mi = 0; mi < 4; mi++)
#pragma unroll
                for (int ni = 0; ni < 4; ni++)
                    MMA16816(acc[mi][ni], &Ah[mi * 4], Bh[ni * 2], Bh[ni * 2 + 1]);
        }
        __syncthreads();

        if (c + 3 < KCH) issue_chunk(smb, buf, c + 3, tid, xh, wh);
        buf = (buf == STAGES - 1) ? 0 : buf + 1;
    }

    // Epilogue: c-frag layout -> direct float2 stores.
    const int r0 = lane >> 2;
    const int cc = 2 * (lane & 3);
#pragma unroll
    for (int mi = 0; mi < 4; mi++) {
#pragma unroll
        for (int ni = 0; ni < 4; ni++) {
            size_t row = mbase + wm + mi * 16 + r0;
            size_t col = nbase + wn + ni * 8 + cc;
            float2 v0 = make_float2(acc[mi][ni][0], acc[mi][ni][1]);
            float2 v1 = make_float2(acc[mi][ni][2], acc[mi][ni][3]);
            *reinterpret_cast<float2*>(out + row * DOUT + col) = v0;
            *reinterpret_cast<float2*>(out + (row + 8) * DOUT + col) = v1;
        }
    }
}

// ---------------------------------------------------------------------------
// Launch
// ---------------------------------------------------------------------------
extern "C" void kernel_launch(void* const* d_in, const int* in_sizes, int n_in,
                              void* d_out, int out_size) {
    const float* x  = (const float*)d_in[0];
    const float* w  = (const float*)d_in[1];
    const int*   mk = (const int*)d_in[2];     // bool upcast to int32 by harness
    float* out = (float*)d_out;

    prep_x_kernel<<<((size_t)MTOT * DIN) / 4 / 256, 256>>>(x);
    prep_w_kernel<<<((size_t)DOUT * DIN) / 4 / 256, 256>>>(w, mk);

    cudaFuncSetAttribute(sparse_linear_hmma_kernel,
                         cudaFuncAttributeMaxDynamicSharedMemorySize, SMEMB);
    sparse_linear_hmma_kernel<<<dim3(NTILES, MTILES), 256, SMEMB>>>(out);
}